// round 15
// baseline (speedup 1.0000x reference)
#include <cuda_runtime.h>
#include <cuda_bf16.h>
#include <math.h>
#include <stdint.h>

#define NN   16384
#define BB   256
#define NPG  64
#define DEG  8
#define EE   (NN*DEG)
#define HH   256
#define FN   133
#define FE   14
#define NPB  4
#define GNB  128

// ---------------- scratch ----------------------------------------------------
__device__ float g_in  [NN*HH];
__device__ float g_hn  [NN*HH];
__device__ float g_tmp [NN*HH];
__device__ float g_cat [NN*3*HH];
__device__ float g_hnl [NN*HH];
__device__ float g_msg [NN*HH];
__device__ float g_xgc [NN*6*HH];    // combined fwd|bwd gate inputs [node][1536]
__device__ float g_hf0 [BB*HH];
__device__ float g_hf1 [BB*HH];
__device__ float g_hb0 [BB*HH];
__device__ float g_hb1 [BB*HH];
__device__ float g_accf[BB*HH];
__device__ float g_accb[BB*HH];
__device__ unsigned g_flags[16*8*32];   // per-(group,jt) flags, 128B apart
// pre-split (N-major, K-padded) weights: hi and lo parts
#define SZ_WN  (HH*160)
#define SZ_WM  (HH*HH)
#define SZ_WLR (HH*3*HH)
#define SZ_WIC (6*HH*HH)             // combined Wif|Wib: N=1536, K=256
__device__ float g_WnH [SZ_WN],  g_WnL [SZ_WN];
__device__ float g_Wm0H[SZ_WM],  g_Wm0L[SZ_WM];
__device__ float g_Wm1H[SZ_WM],  g_Wm1L[SZ_WM];
__device__ float g_WlrH[SZ_WLR], g_WlrL[SZ_WLR];
__device__ float g_WiCH[SZ_WIC], g_WiCL[SZ_WIC];
__device__ float g_biC [6*HH];       // combined bif|bib

__device__ __forceinline__ float sigmoidf_(float x){ return 1.0f/(1.0f+expf(-x)); }

__device__ __forceinline__ void split_tf32(float a, float& hi, float& lo){
    uint32_t u;
    asm("cvt.rna.tf32.f32 %0, %1;" : "=r"(u) : "f"(a));
    hi = __uint_as_float(u);
    lo = a - hi;
}

#define MMA_TF32(c0,c1,c2,c3,a0,a1,a2,a3,b0,b1) \
  asm volatile("mma.sync.aligned.m16n8k8.row.col.f32.tf32.tf32.f32 " \
    "{%0,%1,%2,%3}, {%4,%5,%6,%7}, {%8,%9}, {%0,%1,%2,%3};" \
    : "+f"(c0),"+f"(c1),"+f"(c2),"+f"(c3) \
    : "r"(a0),"r"(a1),"r"(a2),"r"(a3),"r"(b0),"r"(b1))

#define CPA16(dst, src) \
  asm volatile("cp.async.ca.shared.global [%0], [%1], 16;" :: "r"(dst), "l"(src))
#define CPA_COMMIT() asm volatile("cp.async.commit_group;")
#define CPA_WAIT0()  asm volatile("cp.async.wait_group 0;")
#define CPA_WAIT1()  asm volatile("cp.async.wait_group 1;")

// ------ one-shot prep: transpose + K-pad + hi/lo split + bias concat ---------
__global__ void prep_all(const float* __restrict__ Wn,  const float* __restrict__ Wm0,
                         const float* __restrict__ Wm1, const float* __restrict__ Wlr,
                         const float* __restrict__ Wif, const float* __restrict__ Wib,
                         const float* __restrict__ bif, const float* __restrict__ bib)
{
    int idx = blockIdx.x*256 + threadIdx.x;
    const float* W; float* Hd; float* Ld; int K, N, Kpad, local;
    if (idx < SZ_WN){
        W=Wn; Hd=g_WnH; Ld=g_WnL; K=FN; N=HH; Kpad=160; local=idx;
    } else if ((idx -= SZ_WN) < SZ_WM){
        W=Wm0; Hd=g_Wm0H; Ld=g_Wm0L; K=HH; N=HH; Kpad=HH; local=idx;
    } else if ((idx -= SZ_WM) < SZ_WM){
        W=Wm1; Hd=g_Wm1H; Ld=g_Wm1L; K=HH; N=HH; Kpad=HH; local=idx;
    } else if ((idx -= SZ_WM) < SZ_WLR){
        W=Wlr; Hd=g_WlrH; Ld=g_WlrL; K=3*HH; N=HH; Kpad=3*HH; local=idx;
    } else if ((idx -= SZ_WLR) < SZ_WIC){
        int n = idx / HH, k = idx - n*HH;
        const float* Ws = (n < 3*HH) ? Wif : Wib;
        int nc = (n < 3*HH) ? n : n - 3*HH;
        float v = Ws[(size_t)k*(3*HH) + nc];
        float h, l; split_tf32(v, h, l);
        g_WiCH[idx] = h; g_WiCL[idx] = l;
        return;
    } else if ((idx -= SZ_WIC) < 6*HH){
        g_biC[idx] = (idx < 3*HH) ? bif[idx] : bib[idx - 3*HH];
        return;
    } else return;
    int n = local / Kpad, k = local - n*Kpad;
    float v = (k < K) ? W[(size_t)k*N + n] : 0.f;
    float h, l; split_tf32(v, h, l);
    Hd[local] = h; Ld[local] = l;
}

// ------ mma.sync tf32 GEMM (proven): A single-stage, B 2-stage cp.async ------
#define TSZ 4608
#define GE_SMEM (6*TSZ*4)
template<bool RELU, bool MSG>
__global__ __launch_bounds__(256, 2) void mma_gemm(
    int M, int N, int Ktrue, int Kpad,
    const float* __restrict__ A,
    const float* __restrict__ WtH, const float* __restrict__ WtL,
    const float* __restrict__ bias, float* __restrict__ C,
    const float* __restrict__ gb, float* __restrict__ C2)
{
    extern __shared__ float sm[];
    const int tid = threadIdx.x, lane = tid & 31, wid = tid >> 5;
    const int wm = wid >> 2, wn = wid & 3;
    const int row0 = blockIdx.y*128, n0 = blockIdx.x*128;
    const int T = Kpad / 32;
    const uint32_t smu = (uint32_t)__cvta_generic_to_shared(sm);
    const bool al4 = ((Ktrue & 3) == 0);

    float areg[16];

    auto loadB = [&](int t, int st){
        const int k0 = t*32;
        #pragma unroll
        for (int it=0; it<4; it++){
            int idx = it*256 + tid;
            int r = idx >> 3, cc = (idx & 7)*4;
            uint32_t dh = smu + (uint32_t)((((2+2*st)  )*TSZ + r*36 + cc)*4);
            uint32_t dl = smu + (uint32_t)((((3+2*st)  )*TSZ + r*36 + cc)*4);
            CPA16(dh, &WtH[(size_t)(n0+r)*Kpad + k0 + cc]);
            CPA16(dl, &WtL[(size_t)(n0+r)*Kpad + k0 + cc]);
        }
    };
    auto loadA = [&](int t){
        const int k0 = t*32;
        if (al4){
            #pragma unroll
            for (int it=0; it<4; it++){
                int idx = it*256 + tid;
                int r = idx >> 3, cc = (idx & 7)*4;
                int gk = k0 + cc;
                float4 v = (gk < Ktrue) ? *(const float4*)&A[(size_t)(row0+r)*Ktrue + gk]
                                        : make_float4(0.f,0.f,0.f,0.f);
                areg[it*4+0]=v.x; areg[it*4+1]=v.y; areg[it*4+2]=v.z; areg[it*4+3]=v.w;
            }
        } else {
            #pragma unroll
            for (int it=0; it<16; it++){
                int idx = it*256 + tid;
                int r = idx >> 5, cc = idx & 31;
                int gk = k0 + cc;
                areg[it] = (gk < Ktrue) ? A[(size_t)(row0+r)*Ktrue + gk] : 0.f;
            }
        }
    };
    auto storeA = [&](){
        float* Ah = sm;
        float* Al = sm + TSZ;
        if (al4){
            #pragma unroll
            for (int it=0; it<4; it++){
                int idx = it*256 + tid;
                int r = idx >> 3, cc = (idx & 7)*4;
                float4 h4, l4;
                split_tf32(areg[it*4+0], h4.x, l4.x);
                split_tf32(areg[it*4+1], h4.y, l4.y);
                split_tf32(areg[it*4+2], h4.z, l4.z);
                split_tf32(areg[it*4+3], h4.w, l4.w);
                *(float4*)&Ah[r*36 + cc] = h4;
                *(float4*)&Al[r*36 + cc] = l4;
            }
        } else {
            #pragma unroll
            for (int it=0; it<16; it++){
                int idx = it*256 + tid;
                int r = idx >> 5, cc = idx & 31;
                float h, l; split_tf32(areg[it], h, l);
                Ah[r*36 + cc] = h; Al[r*36 + cc] = l;
            }
        }
    };

    float c[4][4][4];
    #pragma unroll
    for (int mt=0; mt<4; mt++)
        #pragma unroll
        for (int nt=0; nt<4; nt++)
            #pragma unroll
            for (int q=0; q<4; q++) c[mt][nt][q] = 0.f;

    loadA(0);
    loadB(0, 0); CPA_COMMIT();

    for (int t = 0; t < T; t++){
        const int st = t & 1;
        if (t > 0) __syncthreads();
        storeA();
        if (t+1 < T){
            loadB(t+1, st^1); CPA_COMMIT();
            loadA(t+1);
            CPA_WAIT1();
        } else {
            CPA_WAIT0();
        }
        __syncthreads();

        const float* Ah = sm;
        const float* Al = sm + TSZ;
        const float* Bh = sm + (2+2*st)*TSZ;
        const float* Bl = sm + (3+2*st)*TSZ;

        #pragma unroll
        for (int kk=0; kk<32; kk+=8){
            uint32_t ah[4][4], alv[4][4], bh[4][2], bl[4][2];
            const int cb = kk + (lane & 3);
            #pragma unroll
            for (int mt=0; mt<4; mt++){
                int r = wm*64 + mt*16 + (lane>>2);
                ah[mt][0] = __float_as_uint(Ah[r*36 + cb]);
                ah[mt][1] = __float_as_uint(Ah[(r+8)*36 + cb]);
                ah[mt][2] = __float_as_uint(Ah[r*36 + cb + 4]);
                ah[mt][3] = __float_as_uint(Ah[(r+8)*36 + cb + 4]);
                alv[mt][0] = __float_as_uint(Al[r*36 + cb]);
                alv[mt][1] = __float_as_uint(Al[(r+8)*36 + cb]);
                alv[mt][2] = __float_as_uint(Al[r*36 + cb + 4]);
                alv[mt][3] = __float_as_uint(Al[(r+8)*36 + cb + 4]);
            }
            #pragma unroll
            for (int nt=0; nt<4; nt++){
                int r = wn*32 + nt*8 + (lane>>2);
                bh[nt][0] = __float_as_uint(Bh[r*36 + cb]);
                bh[nt][1] = __float_as_uint(Bh[r*36 + cb + 4]);
                bl[nt][0] = __float_as_uint(Bl[r*36 + cb]);
                bl[nt][1] = __float_as_uint(Bl[r*36 + cb + 4]);
            }
            // pass 1: hi*hi  (per-accumulator order unchanged: bh, bl, lo)
            #pragma unroll
            for (int mt=0; mt<4; mt++)
                #pragma unroll
                for (int nt=0; nt<4; nt++)
                    MMA_TF32(c[mt][nt][0],c[mt][nt][1],c[mt][nt][2],c[mt][nt][3],
                             ah[mt][0],ah[mt][1],ah[mt][2],ah[mt][3], bh[nt][0],bh[nt][1]);
            // pass 2: hi*lo
            #pragma unroll
            for (int mt=0; mt<4; mt++)
                #pragma unroll
                for (int nt=0; nt<4; nt++)
                    MMA_TF32(c[mt][nt][0],c[mt][nt][1],c[mt][nt][2],c[mt][nt][3],
                             ah[mt][0],ah[mt][1],ah[mt][2],ah[mt][3], bl[nt][0],bl[nt][1]);
            // pass 3: lo*hi
            #pragma unroll
            for (int mt=0; mt<4; mt++)
                #pragma unroll
                for (int nt=0; nt<4; nt++)
                    MMA_TF32(c[mt][nt][0],c[mt][nt][1],c[mt][nt][2],c[mt][nt][3],
                             alv[mt][0],alv[mt][1],alv[mt][2],alv[mt][3], bh[nt][0],bh[nt][1]);
        }
    }

    #pragma unroll
    for (int mt=0; mt<4; mt++){
        int r = row0 + wm*64 + mt*16 + (lane>>2);
        #pragma unroll
        for (int nt=0; nt<4; nt++){
            int col = n0 + wn*32 + nt*8 + 2*(lane & 3);
            float b0v = bias[col], b1v = bias[col+1];
            float v0 = c[mt][nt][0] + b0v, v1 = c[mt][nt][1] + b1v;
            float v2 = c[mt][nt][2] + b0v, v3 = c[mt][nt][3] + b1v;
            if (RELU){ v0=fmaxf(v0,0.f); v1=fmaxf(v1,0.f); v2=fmaxf(v2,0.f); v3=fmaxf(v3,0.f); }
            *(float2*)&C[(size_t)r*N + col]     = make_float2(v0, v1);
            *(float2*)&C[(size_t)(r+8)*N + col] = make_float2(v2, v3);
            if (MSG){
                float g0 = gb[col], g1 = gb[col+1];
                *(float2*)&C2[(size_t)r*N + col] =
                    make_float2(fmaxf(v0+g0,0.f), fmaxf(v1+g1,0.f));
                *(float2*)&C2[(size_t)(r+8)*N + col] =
                    make_float2(fmaxf(v2+g0,0.f), fmaxf(v3+g1,0.f));
            }
        }
    }
}

// ---------- fused aggregate (proven) -----------------------------------------
template<bool HAS_TMP>
__global__ __launch_bounds__(256) void agg_k(
    const float* __restrict__ edge_x, const float* __restrict__ We,
    const float* __restrict__ be,     const float* __restrict__ tmp,
    const int* __restrict__ src,
    const float* __restrict__ hn_in,  float* __restrict__ hn_out)
{
    __shared__ float WeS[FE*HH];
    __shared__ float exs[NPB*DEG*FE];
    __shared__ int   srcS[NPB*DEG];
    const int tid = threadIdx.x;
    const int node0 = blockIdx.x * NPB;

    #pragma unroll
    for (int i = tid; i < FE*HH; i += 256) WeS[i] = We[i];
    for (int i = tid; i < NPB*DEG*FE; i += 256) exs[i] = edge_x[(size_t)node0*DEG*FE + i];
    if (tid < NPB*DEG) srcS[tid] = src[node0*DEG + tid];
    __syncthreads();

    const int j = tid;
    const float bej = be[j];
    #pragma unroll
    for (int nl = 0; nl < NPB; nl++){
        float tv[DEG];
        if (HAS_TMP){
            #pragma unroll
            for (int d=0; d<DEG; d++)
                tv[d] = tmp[(size_t)srcS[nl*DEG+d]*HH + j];
        }
        float s = 0.f, m = -INFINITY;
        #pragma unroll
        for (int d=0; d<DEG; d++){
            float v = bej;
            #pragma unroll
            for (int k=0; k<FE; k++)
                v = fmaf(exs[nl*DEG*FE + d*FE + k], WeS[k*HH + j], v);
            v = fmaxf(v, 0.f);
            if (HAS_TMP) v = fmaxf(v + tv[d], 0.f);
            s += v; m = fmaxf(m, v);
        }
        size_t r = (size_t)(node0+nl)*HH + j;
        hn_out[r] = hn_in[r] + s*m;
    }
}

__global__ __launch_bounds__(256) void cat_k(
    const float* __restrict__ edge_x, const float* __restrict__ We,
    const float* __restrict__ be,     const float* __restrict__ tmp,
    const int* __restrict__ src,
    const float* __restrict__ hn,     const float* __restrict__ in_,
    float* __restrict__ cat)
{
    __shared__ float WeS[FE*HH];
    __shared__ float exs[NPB*DEG*FE];
    __shared__ int   srcS[NPB*DEG];
    const int tid = threadIdx.x;
    const int node0 = blockIdx.x * NPB;

    #pragma unroll
    for (int i = tid; i < FE*HH; i += 256) WeS[i] = We[i];
    for (int i = tid; i < NPB*DEG*FE; i += 256) exs[i] = edge_x[(size_t)node0*DEG*FE + i];
    if (tid < NPB*DEG) srcS[tid] = src[node0*DEG + tid];
    __syncthreads();

    const int j = tid;
    const float bej = be[j];
    #pragma unroll
    for (int nl = 0; nl < NPB; nl++){
        float tv[DEG];
        #pragma unroll
        for (int d=0; d<DEG; d++)
            tv[d] = tmp[(size_t)srcS[nl*DEG+d]*HH + j];
        float s = 0.f, m = -INFINITY;
        #pragma unroll
        for (int d=0; d<DEG; d++){
            float v = bej;
            #pragma unroll
            for (int k=0; k<FE; k++)
                v = fmaf(exs[nl*DEG*FE + d*FE + k], WeS[k*HH + j], v);
            v = fmaxf(v, 0.f);
            v = fmaxf(v + tv[d], 0.f);
            s += v; m = fmaxf(m, v);
        }
        int node = node0 + nl;
        size_t r = (size_t)node*3*HH;
        cat[r + j]        = s*m;
        cat[r + HH + j]   = hn[(size_t)node*HH + j];
        cat[r + 2*HH + j] = in_[(size_t)node*HH + j];
    }
}

__global__ void init_h0_k(const float* __restrict__ hnl,
                          float* __restrict__ hf, float* __restrict__ hb,
                          float* __restrict__ accf, float* __restrict__ accb)
{
    int b = blockIdx.x, j = threadIdx.x;
    float m = -INFINITY;
    #pragma unroll 8
    for (int t=0; t<NPG; t++)
        m = fmaxf(m, hnl[((size_t)b*NPG + t)*HH + j]);
    hf[b*HH+j] = m; hb[b*HH+j] = m;
    accf[b*HH+j] = 0.f; accb[b*HH+j] = 0.f;
}

__global__ void bar_reset_k(){
    if (threadIdx.x < 128) g_flags[threadIdx.x*32] = 0u;
}

// ---------- persistent GRU (proven math) with distributed flag barrier -------
#define KP 260
#define WS_FLOATS (96*KP)
#define HS_FLOATS (32*KP)
#define GRU_SMEM ((WS_FLOATS + 2*HS_FLOATS)*4 + WS_FLOATS*2)
__global__ __launch_bounds__(256) void gru_persist(
    const float* __restrict__ xgc,
    const float* __restrict__ Whf, const float* __restrict__ Whb,
    const float* __restrict__ bhf, const float* __restrict__ bhb,
    float* __restrict__ hf0, float* __restrict__ hf1,
    float* __restrict__ hb0, float* __restrict__ hb1,
    float* __restrict__ accf, float* __restrict__ accb)
{
    extern __shared__ float smf[];
    float* WSH = smf;
    float* HSH = smf + WS_FLOATS;
    float* HSL = HSH + HS_FLOATS;
    __nv_bfloat16* WSL = (__nv_bfloat16*)(HSL + HS_FLOATS);
    __shared__ float bhs[96];

    const int bid = blockIdx.x;
    const int jt = bid & 7, gt = (bid >> 3) & 7, dir = bid >> 6;
    const int j0 = jt*32, g0 = gt*32;
    const int grp = (gt << 1) | dir;
    unsigned* flagbase = &g_flags[grp*8*32];
    unsigned* myflag   = flagbase + jt*32;
    const float* Wh = dir ? Whb : Whf;
    const float* bh = dir ? bhb : bhf;
    float* b0buf = dir ? hb0 : hf0;
    float* b1buf = dir ? hb1 : hf1;
    float* accg  = dir ? accb : accf;
    const float* xbase = xgc + (size_t)dir*(3*HH);

    const int tid = threadIdx.x, lane = tid & 31, wid = tid >> 5;
    const int wm = wid >> 2, wj = wid & 3;

    for (int i = tid; i < 96*256; i += 256){
        int n = i >> 8, k = i & 255;
        int gate = n >> 5, jj = n & 31;
        float w = Wh[(size_t)k*(3*HH) + gate*HH + j0 + jj];
        float h, l; split_tf32(w, h, l);
        WSH[n*KP + k] = h;
        WSL[n*KP + k] = __float2bfloat16(l);
    }
    if (tid < 96){
        int gate = tid >> 5, jj = tid & 31;
        bhs[tid] = bh[gate*HH + j0 + jj];
    }

    float acc[4] = {0.f, 0.f, 0.f, 0.f};
    const int lr = lane >> 2, lc = lane & 3;

    for (int s = 0; s < NPG; s++){
        const float* hin = (s & 1) ? b1buf : b0buf;
        float*       hout= (s & 1) ? b0buf : b1buf;
        const int t = dir ? (NPG-1-s) : s;

        // prefetch x (independent of h) so LDG latency overlaps h/MMA
        float xv[4][3];
        #pragma unroll
        for (int dr=0; dr<2; dr++){
            const int g = g0 + wm*16 + lr + dr*8;
            const float* x = xbase + ((size_t)g*NPG + t)*(6*HH);
            #pragma unroll
            for (int dc=0; dc<2; dc++){
                const int j = j0 + wj*8 + 2*lc + dc;
                xv[dr*2+dc][0] = x[j];
                xv[dr*2+dc][1] = x[HH + j];
                xv[dr*2+dc][2] = x[2*HH + j];
            }
        }

        #pragma unroll 4
        for (int i = tid; i < 32*256; i += 256){
            int g = i >> 8, k = i & 255;
            float v = hin[(size_t)(g0+g)*HH + k];
            float h, l; split_tf32(v, h, l);
            HSH[g*KP + k] = h;
            HSL[g*KP + k] = l;
        }
        __syncthreads();

        float c[3][4];
        #pragma unroll
        for (int q=0;q<3;q++)
            #pragma unroll
            for (int p=0;p<4;p++) c[q][p]=0.f;

        const int arow = (wm*16 + lr)*KP;
        #pragma unroll 4
        for (int kt = 0; kt < 32; kt++){
            const int ac = kt*8 + lc;
            uint32_t a0 = __float_as_uint(HSH[arow + ac]);
            uint32_t a1 = __float_as_uint(HSH[arow + 8*KP + ac]);
            uint32_t a2 = __float_as_uint(HSH[arow + ac + 4]);
            uint32_t a3 = __float_as_uint(HSH[arow + 8*KP + ac + 4]);
            uint32_t l0 = __float_as_uint(HSL[arow + ac]);
            uint32_t l1 = __float_as_uint(HSL[arow + 8*KP + ac]);
            uint32_t l2 = __float_as_uint(HSL[arow + ac + 4]);
            uint32_t l3 = __float_as_uint(HSL[arow + 8*KP + ac + 4]);
            #pragma unroll
            for (int q=0;q<3;q++){
                const int brow = (q*32 + wj*8 + lr)*KP;
                uint32_t b0 = __float_as_uint(WSH[brow + ac]);
                uint32_t b1 = __float_as_uint(WSH[brow + ac + 4]);
                uint32_t bl0 = __float_as_uint(__bfloat162float(WSL[brow + ac]));
                uint32_t bl1 = __float_as_uint(__bfloat162float(WSL[brow + ac + 4]));
                MMA_TF32(c[q][0],c[q][1],c[q][2],c[q][3], a0,a1,a2,a3, b0,b1);
                MMA_TF32(c[q][0],c[q][1],c[q][2],c[q][3], a0,a1,a2,a3, bl0,bl1);
                MMA_TF32(c[q][0],c[q][1],c[q][2],c[q][3], l0,l1,l2,l3, b0,b1);
            }
        }

        #pragma unroll
        for (int dr=0; dr<2; dr++){
            const int gl = wm*16 + lr + dr*8;
            const int g = g0 + gl;
            #pragma unroll
            for (int dc=0; dc<2; dc++){
                const int jl = wj*8 + 2*lc + dc;
                const int j = j0 + jl;
                const int ci = dr*2 + dc;
                float rv = sigmoidf_(xv[ci][0] + c[0][ci] + bhs[jl]);
                float zv = sigmoidf_(xv[ci][1] + c[1][ci] + bhs[32+jl]);
                float nv = tanhf    (xv[ci][2] + rv*(c[2][ci] + bhs[64+jl]));
                float hold = HSH[gl*KP + j] + HSL[gl*KP + j];
                float hv = (1.0f - zv)*nv + zv*hold;
                acc[ci] += hv;
                hout[(size_t)g*HH + j] = hv;
            }
        }

        // distributed flag barrier: own-flag release, parallel peer-acquire
        if (s < NPG-1){
            __syncthreads();
            if (tid == 0){
                asm volatile("st.release.gpu.u32 [%0], %1;"
                             :: "l"(myflag), "r"((unsigned)(s+1)) : "memory");
            }
            if (tid < 8){
                unsigned* pf = flagbase + tid*32;
                unsigned v;
                do {
                    asm volatile("ld.acquire.gpu.u32 %0, [%1];"
                                 : "=r"(v) : "l"(pf) : "memory");
                } while (v < (unsigned)(s+1));
            }
            __syncthreads();
        }
    }

    #pragma unroll
    for (int dr=0; dr<2; dr++){
        const int g = g0 + wm*16 + lr + dr*8;
        #pragma unroll
        for (int dc=0; dc<2; dc++){
            const int j = j0 + wj*8 + 2*lc + dc;
            accg[(size_t)g*HH + j] = acc[dr*2 + dc];
        }
    }
}

__global__ void readout_k(const float* __restrict__ accf, const float* __restrict__ accb,
                          const float* __restrict__ W1, const float* __restrict__ b1,
                          const float* __restrict__ W2, const float* __restrict__ b2,
                          float* __restrict__ out)
{
    int b = blockIdx.x, j = threadIdx.x;
    __shared__ float gsh[2*HH];
    __shared__ float red[HH];
    gsh[j]      = accf[b*HH + j] * (1.0f/NPG);
    gsh[HH + j] = accb[b*HH + j] * (1.0f/NPG);
    __syncthreads();
    float y = b1[j];
    #pragma unroll 8
    for (int k=0; k<2*HH; k++)
        y = fmaf(gsh[k], W1[k*HH + j], y);
    y = fmaxf(y, 0.f);
    red[j] = y * W2[j];
    __syncthreads();
    for (int s=128; s>0; s>>=1){
        if (j < s) red[j] += red[j+s];
        __syncthreads();
    }
    if (j == 0) out[b] = red[0] + b2[0];
}

// =============================================================================
extern "C" void kernel_launch(void* const* d_in, const int* in_sizes, int n_in,
                              void* d_out, int out_size)
{
    const float* node_x = (const float*)d_in[0];
    const float* edge_x = (const float*)d_in[1];
    const int*   src    = (const int*)  d_in[2];
    const float* Wn  = (const float*)d_in[4];  const float* bn  = (const float*)d_in[5];
    const float* We  = (const float*)d_in[6];  const float* be  = (const float*)d_in[7];
    const float* Wm0 = (const float*)d_in[8];  const float* bm0 = (const float*)d_in[9];
    const float* Wm1 = (const float*)d_in[10]; const float* bm1 = (const float*)d_in[11];
    const float* Wlr = (const float*)d_in[12]; const float* blr = (const float*)d_in[13];
    const float* gbias = (const float*)d_in[14];
    const float* Wif = (const float*)d_in[15]; const float* Whf = (const float*)d_in[16];
    const float* bif = (const float*)d_in[17]; const float* bhf = (const float*)d_in[18];
    const float* Wib = (const float*)d_in[19]; const float* Whb = (const float*)d_in[20];
    const float* bib = (const float*)d_in[21]; const float* bhb = (const float*)d_in[22];
    const float* W1  = (const float*)d_in[23]; const float* b1  = (const float*)d_in[24];
    const float* W2  = (const float*)d_in[25]; const float* b2  = (const float*)d_in[26];
    float* out = (float*)d_out;

    float *p_in,*p_hn,*p_tmp,*p_cat,*p_hnl,*p_msg,*p_xgc;
    float *p_hf0,*p_hf1,*p_hb0,*p_hb1,*p_accf,*p_accb;
    float *p_WnH,*p_WnL,*p_Wm0H,*p_Wm0L,*p_Wm1H,*p_Wm1L;
    float *p_WlrH,*p_WlrL,*p_WiCH,*p_WiCL,*p_biC;
    cudaGetSymbolAddress((void**)&p_in,  g_in);
    cudaGetSymbolAddress((void**)&p_hn,  g_hn);
    cudaGetSymbolAddress((void**)&p_tmp, g_tmp);
    cudaGetSymbolAddress((void**)&p_cat, g_cat);
    cudaGetSymbolAddress((void**)&p_hnl, g_hnl);
    cudaGetSymbolAddress((void**)&p_msg, g_msg);
    cudaGetSymbolAddress((void**)&p_xgc, g_xgc);
    cudaGetSymbolAddress((void**)&p_hf0, g_hf0);
    cudaGetSymbolAddress((void**)&p_hf1, g_hf1);
    cudaGetSymbolAddress((void**)&p_hb0, g_hb0);
    cudaGetSymbolAddress((void**)&p_hb1, g_hb1);
    cudaGetSymbolAddress((void**)&p_accf, g_accf);
    cudaGetSymbolAddress((void**)&p_accb, g_accb);
    cudaGetSymbolAddress((void**)&p_WnH,  g_WnH);  cudaGetSymbolAddress((void**)&p_WnL,  g_WnL);
    cudaGetSymbolAddress((void**)&p_Wm0H, g_Wm0H); cudaGetSymbolAddress((void**)&p_Wm0L, g_Wm0L);
    cudaGetSymbolAddress((void**)&p_Wm1H, g_Wm1H); cudaGetSymbolAddress((void**)&p_Wm1L, g_Wm1L);
    cudaGetSymbolAddress((void**)&p_WlrH, g_WlrH); cudaGetSymbolAddress((void**)&p_WlrL, g_WlrL);
    cudaGetSymbolAddress((void**)&p_WiCH, g_WiCH); cudaGetSymbolAddress((void**)&p_WiCL, g_WiCL);
    cudaGetSymbolAddress((void**)&p_biC,  g_biC);

    cudaFuncSetAttribute(mma_gemm<true,false>,  cudaFuncAttributeMaxDynamicSharedMemorySize, GE_SMEM);
    cudaFuncSetAttribute(mma_gemm<false,false>, cudaFuncAttributeMaxDynamicSharedMemorySize, GE_SMEM);
    cudaFuncSetAttribute(mma_gemm<false,true>,  cudaFuncAttributeMaxDynamicSharedMemorySize, GE_SMEM);
    cudaFuncSetAttribute(gru_persist,           cudaFuncAttributeMaxDynamicSharedMemorySize, GRU_SMEM);

    // 0) one-shot weight prep (transpose + pad + hi/lo split + bias concat)
    int prep_total = SZ_WN + 2*SZ_WM + SZ_WLR + SZ_WIC + 6*HH;
    prep_all<<<(prep_total+255)/256, 256>>>(Wn, Wm0, Wm1, Wlr, Wif, Wib, bif, bib);

    // 1) node embedding
    mma_gemm<true,false><<<dim3(2,128), 256, GE_SMEM>>>(NN, HH, FN, 160,
        node_x, p_WnH, p_WnL, bn, p_in, nullptr, nullptr);

    // 2) round 1
    agg_k<false><<<NN/NPB, 256>>>(edge_x, We, be, nullptr, src, p_in, p_hn);
    mma_gemm<false,false><<<dim3(2,128), 256, GE_SMEM>>>(NN, HH, HH, HH,
        p_hn, p_Wm0H, p_Wm0L, bm0, p_tmp, nullptr, nullptr);

    // 3) round 2
    agg_k<true><<<NN/NPB, 256>>>(edge_x, We, be, p_tmp, src, p_hn, p_hn);
    mma_gemm<false,false><<<dim3(2,128), 256, GE_SMEM>>>(NN, HH, HH, HH,
        p_hn, p_Wm1H, p_Wm1L, bm1, p_tmp, nullptr, nullptr);

    // 4) final aggregate + concat + Wlr (+fused msg epilogue)
    cat_k<<<NN/NPB, 256>>>(edge_x, We, be, p_tmp, src, p_hn, p_in, p_cat);
    mma_gemm<false,true><<<dim3(2,128), 256, GE_SMEM>>>(NN, HH, 3*HH, 3*HH,
        p_cat, p_WlrH, p_WlrL, blr, p_hnl, gbias, p_msg);

    // 5) GRU setup: combined fwd|bwd gate-input GEMM (N=1536)
    init_h0_k<<<BB, HH>>>(p_hnl, p_hf0, p_hb0, p_accf, p_accb);
    mma_gemm<false,false><<<dim3(12,128), 256, GE_SMEM>>>(NN, 6*HH, HH, HH,
        p_msg, p_WiCH, p_WiCL, p_biC, p_xgc, nullptr, nullptr);

    // 6) persistent GRU (tensor-core recurrent GEMM, distributed flag barrier)
    bar_reset_k<<<1,128>>>();
    gru_persist<<<GNB, 256, GRU_SMEM>>>(p_xgc, Whf, Whb, bhf, bhb,
                                        p_hf0, p_hf1, p_hb0, p_hb1, p_accf, p_accb);

    // 7) readout
    readout_k<<<BB, HH>>>(p_accf, p_accb, W1, b1, W2, b2, out);
}

// round 16
// speedup vs baseline: 1.0345x; 1.0345x over previous
#include <cuda_runtime.h>
#include <cuda_bf16.h>
#include <math.h>
#include <stdint.h>

#define NN   16384
#define BB   256
#define NPG  64
#define DEG  8
#define EE   (NN*DEG)
#define HH   256
#define FN   133
#define FE   14
#define NPB  8
#define GNB  128

// ---------------- scratch ----------------------------------------------------
__device__ float g_in  [NN*HH];
__device__ float g_hn  [NN*HH];
__device__ float g_tmp [NN*HH];
__device__ float g_cat [NN*3*HH];
__device__ float g_hnl [NN*HH];
__device__ float g_msg [NN*HH];
__device__ float g_xgc [NN*6*HH];    // combined fwd|bwd gate inputs [node][1536]
__device__ float g_hf0 [BB*HH];
__device__ float g_hf1 [BB*HH];
__device__ float g_hb0 [BB*HH];
__device__ float g_hb1 [BB*HH];
__device__ float g_accf[BB*HH];
__device__ float g_accb[BB*HH];
__device__ unsigned g_bars[16*32];   // 16 group barriers, 128B apart
// pre-split (N-major, K-padded) weights: hi and lo parts
#define SZ_WN  (HH*160)
#define SZ_WM  (HH*HH)
#define SZ_WLR (HH*3*HH)
#define SZ_WIC (6*HH*HH)             // combined Wif|Wib: N=1536, K=256
__device__ float g_WnH [SZ_WN],  g_WnL [SZ_WN];
__device__ float g_Wm0H[SZ_WM],  g_Wm0L[SZ_WM];
__device__ float g_Wm1H[SZ_WM],  g_Wm1L[SZ_WM];
__device__ float g_WlrH[SZ_WLR], g_WlrL[SZ_WLR];
__device__ float g_WiCH[SZ_WIC], g_WiCL[SZ_WIC];
__device__ float g_biC [6*HH];       // combined bif|bib

__device__ __forceinline__ float sigmoidf_(float x){ return 1.0f/(1.0f+expf(-x)); }

__device__ __forceinline__ void split_tf32(float a, float& hi, float& lo){
    uint32_t u;
    asm("cvt.rna.tf32.f32 %0, %1;" : "=r"(u) : "f"(a));
    hi = __uint_as_float(u);
    lo = a - hi;
}

#define MMA_TF32(c0,c1,c2,c3,a0,a1,a2,a3,b0,b1) \
  asm volatile("mma.sync.aligned.m16n8k8.row.col.f32.tf32.tf32.f32 " \
    "{%0,%1,%2,%3}, {%4,%5,%6,%7}, {%8,%9}, {%0,%1,%2,%3};" \
    : "+f"(c0),"+f"(c1),"+f"(c2),"+f"(c3) \
    : "r"(a0),"r"(a1),"r"(a2),"r"(a3),"r"(b0),"r"(b1))

#define CPA16(dst, src) \
  asm volatile("cp.async.ca.shared.global [%0], [%1], 16;" :: "r"(dst), "l"(src))
#define CPA_COMMIT() asm volatile("cp.async.commit_group;")
#define CPA_WAIT0()  asm volatile("cp.async.wait_group 0;")
#define CPA_WAIT1()  asm volatile("cp.async.wait_group 1;")

// ------ one-shot prep: transpose + K-pad + hi/lo split + bias concat ---------
__global__ void prep_all(const float* __restrict__ Wn,  const float* __restrict__ Wm0,
                         const float* __restrict__ Wm1, const float* __restrict__ Wlr,
                         const float* __restrict__ Wif, const float* __restrict__ Wib,
                         const float* __restrict__ bif, const float* __restrict__ bib)
{
    int idx = blockIdx.x*256 + threadIdx.x;
    const float* W; float* Hd; float* Ld; int K, N, Kpad, local;
    if (idx < SZ_WN){
        W=Wn; Hd=g_WnH; Ld=g_WnL; K=FN; N=HH; Kpad=160; local=idx;
    } else if ((idx -= SZ_WN) < SZ_WM){
        W=Wm0; Hd=g_Wm0H; Ld=g_Wm0L; K=HH; N=HH; Kpad=HH; local=idx;
    } else if ((idx -= SZ_WM) < SZ_WM){
        W=Wm1; Hd=g_Wm1H; Ld=g_Wm1L; K=HH; N=HH; Kpad=HH; local=idx;
    } else if ((idx -= SZ_WM) < SZ_WLR){
        W=Wlr; Hd=g_WlrH; Ld=g_WlrL; K=3*HH; N=HH; Kpad=3*HH; local=idx;
    } else if ((idx -= SZ_WLR) < SZ_WIC){
        int n = idx / HH, k = idx - n*HH;
        const float* Ws = (n < 3*HH) ? Wif : Wib;
        int nc = (n < 3*HH) ? n : n - 3*HH;
        float v = Ws[(size_t)k*(3*HH) + nc];
        float h, l; split_tf32(v, h, l);
        g_WiCH[idx] = h; g_WiCL[idx] = l;
        return;
    } else if ((idx -= SZ_WIC) < 6*HH){
        g_biC[idx] = (idx < 3*HH) ? bif[idx] : bib[idx - 3*HH];
        return;
    } else return;
    int n = local / Kpad, k = local - n*Kpad;
    float v = (k < K) ? W[(size_t)k*N + n] : 0.f;
    float h, l; split_tf32(v, h, l);
    Hd[local] = h; Ld[local] = l;
}

// ------ mma.sync tf32 GEMM (proven): A single-stage, B 2-stage cp.async ------
#define TSZ 4608
#define GE_SMEM (6*TSZ*4)
template<bool RELU, bool MSG>
__global__ __launch_bounds__(256, 2) void mma_gemm(
    int M, int N, int Ktrue, int Kpad,
    const float* __restrict__ A,
    const float* __restrict__ WtH, const float* __restrict__ WtL,
    const float* __restrict__ bias, float* __restrict__ C,
    const float* __restrict__ gb, float* __restrict__ C2)
{
    extern __shared__ float sm[];
    const int tid = threadIdx.x, lane = tid & 31, wid = tid >> 5;
    const int wm = wid >> 2, wn = wid & 3;
    const int row0 = blockIdx.y*128, n0 = blockIdx.x*128;
    const int T = Kpad / 32;
    const uint32_t smu = (uint32_t)__cvta_generic_to_shared(sm);
    const bool al4 = ((Ktrue & 3) == 0);

    float areg[16];

    auto loadB = [&](int t, int st){
        const int k0 = t*32;
        #pragma unroll
        for (int it=0; it<4; it++){
            int idx = it*256 + tid;
            int r = idx >> 3, cc = (idx & 7)*4;
            uint32_t dh = smu + (uint32_t)((((2+2*st)  )*TSZ + r*36 + cc)*4);
            uint32_t dl = smu + (uint32_t)((((3+2*st)  )*TSZ + r*36 + cc)*4);
            CPA16(dh, &WtH[(size_t)(n0+r)*Kpad + k0 + cc]);
            CPA16(dl, &WtL[(size_t)(n0+r)*Kpad + k0 + cc]);
        }
    };
    auto loadA = [&](int t){
        const int k0 = t*32;
        if (al4){
            #pragma unroll
            for (int it=0; it<4; it++){
                int idx = it*256 + tid;
                int r = idx >> 3, cc = (idx & 7)*4;
                int gk = k0 + cc;
                float4 v = (gk < Ktrue) ? *(const float4*)&A[(size_t)(row0+r)*Ktrue + gk]
                                        : make_float4(0.f,0.f,0.f,0.f);
                areg[it*4+0]=v.x; areg[it*4+1]=v.y; areg[it*4+2]=v.z; areg[it*4+3]=v.w;
            }
        } else {
            #pragma unroll
            for (int it=0; it<16; it++){
                int idx = it*256 + tid;
                int r = idx >> 5, cc = idx & 31;
                int gk = k0 + cc;
                areg[it] = (gk < Ktrue) ? A[(size_t)(row0+r)*Ktrue + gk] : 0.f;
            }
        }
    };
    auto storeA = [&](){
        float* Ah = sm;
        float* Al = sm + TSZ;
        if (al4){
            #pragma unroll
            for (int it=0; it<4; it++){
                int idx = it*256 + tid;
                int r = idx >> 3, cc = (idx & 7)*4;
                float4 h4, l4;
                split_tf32(areg[it*4+0], h4.x, l4.x);
                split_tf32(areg[it*4+1], h4.y, l4.y);
                split_tf32(areg[it*4+2], h4.z, l4.z);
                split_tf32(areg[it*4+3], h4.w, l4.w);
                *(float4*)&Ah[r*36 + cc] = h4;
                *(float4*)&Al[r*36 + cc] = l4;
            }
        } else {
            #pragma unroll
            for (int it=0; it<16; it++){
                int idx = it*256 + tid;
                int r = idx >> 5, cc = idx & 31;
                float h, l; split_tf32(areg[it], h, l);
                Ah[r*36 + cc] = h; Al[r*36 + cc] = l;
            }
        }
    };

    float c[4][4][4];
    #pragma unroll
    for (int mt=0; mt<4; mt++)
        #pragma unroll
        for (int nt=0; nt<4; nt++)
            #pragma unroll
            for (int q=0; q<4; q++) c[mt][nt][q] = 0.f;

    loadA(0);
    loadB(0, 0); CPA_COMMIT();

    for (int t = 0; t < T; t++){
        const int st = t & 1;
        if (t > 0) __syncthreads();
        storeA();
        if (t+1 < T){
            loadB(t+1, st^1); CPA_COMMIT();
            loadA(t+1);
            CPA_WAIT1();
        } else {
            CPA_WAIT0();
        }
        __syncthreads();

        const float* Ah = sm;
        const float* Al = sm + TSZ;
        const float* Bh = sm + (2+2*st)*TSZ;
        const float* Bl = sm + (3+2*st)*TSZ;

        #pragma unroll
        for (int kk=0; kk<32; kk+=8){
            uint32_t ah[4][4], alv[4][4], bh[4][2], bl[4][2];
            const int cb = kk + (lane & 3);
            #pragma unroll
            for (int mt=0; mt<4; mt++){
                int r = wm*64 + mt*16 + (lane>>2);
                ah[mt][0] = __float_as_uint(Ah[r*36 + cb]);
                ah[mt][1] = __float_as_uint(Ah[(r+8)*36 + cb]);
                ah[mt][2] = __float_as_uint(Ah[r*36 + cb + 4]);
                ah[mt][3] = __float_as_uint(Ah[(r+8)*36 + cb + 4]);
                alv[mt][0] = __float_as_uint(Al[r*36 + cb]);
                alv[mt][1] = __float_as_uint(Al[(r+8)*36 + cb]);
                alv[mt][2] = __float_as_uint(Al[r*36 + cb + 4]);
                alv[mt][3] = __float_as_uint(Al[(r+8)*36 + cb + 4]);
            }
            #pragma unroll
            for (int nt=0; nt<4; nt++){
                int r = wn*32 + nt*8 + (lane>>2);
                bh[nt][0] = __float_as_uint(Bh[r*36 + cb]);
                bh[nt][1] = __float_as_uint(Bh[r*36 + cb + 4]);
                bl[nt][0] = __float_as_uint(Bl[r*36 + cb]);
                bl[nt][1] = __float_as_uint(Bl[r*36 + cb + 4]);
            }
            #pragma unroll
            for (int mt=0; mt<4; mt++)
                #pragma unroll
                for (int nt=0; nt<4; nt++){
                    MMA_TF32(c[mt][nt][0],c[mt][nt][1],c[mt][nt][2],c[mt][nt][3],
                             ah[mt][0],ah[mt][1],ah[mt][2],ah[mt][3], bh[nt][0],bh[nt][1]);
                    MMA_TF32(c[mt][nt][0],c[mt][nt][1],c[mt][nt][2],c[mt][nt][3],
                             ah[mt][0],ah[mt][1],ah[mt][2],ah[mt][3], bl[nt][0],bl[nt][1]);
                    MMA_TF32(c[mt][nt][0],c[mt][nt][1],c[mt][nt][2],c[mt][nt][3],
                             alv[mt][0],alv[mt][1],alv[mt][2],alv[mt][3], bh[nt][0],bh[nt][1]);
                }
        }
    }

    #pragma unroll
    for (int mt=0; mt<4; mt++){
        int r = row0 + wm*64 + mt*16 + (lane>>2);
        #pragma unroll
        for (int nt=0; nt<4; nt++){
            int col = n0 + wn*32 + nt*8 + 2*(lane & 3);
            float b0v = bias[col], b1v = bias[col+1];
            float v0 = c[mt][nt][0] + b0v, v1 = c[mt][nt][1] + b1v;
            float v2 = c[mt][nt][2] + b0v, v3 = c[mt][nt][3] + b1v;
            if (RELU){ v0=fmaxf(v0,0.f); v1=fmaxf(v1,0.f); v2=fmaxf(v2,0.f); v3=fmaxf(v3,0.f); }
            *(float2*)&C[(size_t)r*N + col]     = make_float2(v0, v1);
            *(float2*)&C[(size_t)(r+8)*N + col] = make_float2(v2, v3);
            if (MSG){
                float g0 = gb[col], g1 = gb[col+1];
                *(float2*)&C2[(size_t)r*N + col] =
                    make_float2(fmaxf(v0+g0,0.f), fmaxf(v1+g1,0.f));
                *(float2*)&C2[(size_t)(r+8)*N + col] =
                    make_float2(fmaxf(v2+g0,0.f), fmaxf(v3+g1,0.f));
            }
        }
    }
}

// ---------- fused aggregate (proven, NPB=8) ----------------------------------
template<bool HAS_TMP>
__global__ __launch_bounds__(256) void agg_k(
    const float* __restrict__ edge_x, const float* __restrict__ We,
    const float* __restrict__ be,     const float* __restrict__ tmp,
    const int* __restrict__ src,
    const float* __restrict__ hn_in,  float* __restrict__ hn_out)
{
    __shared__ float WeS[FE*HH];
    __shared__ float exs[NPB*DEG*FE];
    __shared__ int   srcS[NPB*DEG];
    const int tid = threadIdx.x;
    const int node0 = blockIdx.x * NPB;

    #pragma unroll
    for (int i = tid; i < FE*HH; i += 256) WeS[i] = We[i];
    for (int i = tid; i < NPB*DEG*FE; i += 256) exs[i] = edge_x[(size_t)node0*DEG*FE + i];
    if (tid < NPB*DEG) srcS[tid] = src[node0*DEG + tid];
    __syncthreads();

    const int j = tid;
    const float bej = be[j];
    #pragma unroll
    for (int nl = 0; nl < NPB; nl++){
        float tv[DEG];
        if (HAS_TMP){
            #pragma unroll
            for (int d=0; d<DEG; d++)
                tv[d] = tmp[(size_t)srcS[nl*DEG+d]*HH + j];
        }
        float s = 0.f, m = -INFINITY;
        #pragma unroll
        for (int d=0; d<DEG; d++){
            float v = bej;
            #pragma unroll
            for (int k=0; k<FE; k++)
                v = fmaf(exs[nl*DEG*FE + d*FE + k], WeS[k*HH + j], v);
            v = fmaxf(v, 0.f);
            if (HAS_TMP) v = fmaxf(v + tv[d], 0.f);
            s += v; m = fmaxf(m, v);
        }
        size_t r = (size_t)(node0+nl)*HH + j;
        hn_out[r] = hn_in[r] + s*m;
    }
}

__global__ __launch_bounds__(256) void cat_k(
    const float* __restrict__ edge_x, const float* __restrict__ We,
    const float* __restrict__ be,     const float* __restrict__ tmp,
    const int* __restrict__ src,
    const float* __restrict__ hn,     const float* __restrict__ in_,
    float* __restrict__ cat)
{
    __shared__ float WeS[FE*HH];
    __shared__ float exs[NPB*DEG*FE];
    __shared__ int   srcS[NPB*DEG];
    const int tid = threadIdx.x;
    const int node0 = blockIdx.x * NPB;

    #pragma unroll
    for (int i = tid; i < FE*HH; i += 256) WeS[i] = We[i];
    for (int i = tid; i < NPB*DEG*FE; i += 256) exs[i] = edge_x[(size_t)node0*DEG*FE + i];
    if (tid < NPB*DEG) srcS[tid] = src[node0*DEG + tid];
    __syncthreads();

    const int j = tid;
    const float bej = be[j];
    #pragma unroll
    for (int nl = 0; nl < NPB; nl++){
        float tv[DEG];
        #pragma unroll
        for (int d=0; d<DEG; d++)
            tv[d] = tmp[(size_t)srcS[nl*DEG+d]*HH + j];
        float s = 0.f, m = -INFINITY;
        #pragma unroll
        for (int d=0; d<DEG; d++){
            float v = bej;
            #pragma unroll
            for (int k=0; k<FE; k++)
                v = fmaf(exs[nl*DEG*FE + d*FE + k], WeS[k*HH + j], v);
            v = fmaxf(v, 0.f);
            v = fmaxf(v + tv[d], 0.f);
            s += v; m = fmaxf(m, v);
        }
        int node = node0 + nl;
        size_t r = (size_t)node*3*HH;
        cat[r + j]        = s*m;
        cat[r + HH + j]   = hn[(size_t)node*HH + j];
        cat[r + 2*HH + j] = in_[(size_t)node*HH + j];
    }
}

__global__ void init_h0_k(const float* __restrict__ hnl,
                          float* __restrict__ hf, float* __restrict__ hb,
                          float* __restrict__ accf, float* __restrict__ accb)
{
    int b = blockIdx.x, j = threadIdx.x;
    float m = -INFINITY;
    #pragma unroll 8
    for (int t=0; t<NPG; t++)
        m = fmaxf(m, hnl[((size_t)b*NPG + t)*HH + j]);
    hf[b*HH+j] = m; hb[b*HH+j] = m;
    accf[b*HH+j] = 0.f; accb[b*HH+j] = 0.f;
}

__global__ void bar_reset_k(){
    if (threadIdx.x < 16) g_bars[threadIdx.x*32] = 0u;
}

// ---------- persistent GRU (R14-proven) + float2 x/h vector accesses ---------
#define KP 260
#define WS_FLOATS (96*KP)
#define HS_FLOATS (32*KP)
#define GRU_SMEM ((WS_FLOATS + 2*HS_FLOATS)*4 + WS_FLOATS*2)
__global__ __launch_bounds__(256) void gru_persist(
    const float* __restrict__ xgc,
    const float* __restrict__ Whf, const float* __restrict__ Whb,
    const float* __restrict__ bhf, const float* __restrict__ bhb,
    float* __restrict__ hf0, float* __restrict__ hf1,
    float* __restrict__ hb0, float* __restrict__ hb1,
    float* __restrict__ accf, float* __restrict__ accb)
{
    extern __shared__ float smf[];
    float* WSH = smf;
    float* HSH = smf + WS_FLOATS;
    float* HSL = HSH + HS_FLOATS;
    __nv_bfloat16* WSL = (__nv_bfloat16*)(HSL + HS_FLOATS);
    __shared__ float bhs[96];

    const int bid = blockIdx.x;
    const int jt = bid & 7, gt = (bid >> 3) & 7, dir = bid >> 6;
    const int j0 = jt*32, g0 = gt*32;
    const int grp = (gt << 1) | dir;
    unsigned* bar = &g_bars[grp*32];
    const float* Wh = dir ? Whb : Whf;
    const float* bh = dir ? bhb : bhf;
    float* b0buf = dir ? hb0 : hf0;
    float* b1buf = dir ? hb1 : hf1;
    float* accg  = dir ? accb : accf;
    const float* xbase = xgc + (size_t)dir*(3*HH);

    const int tid = threadIdx.x, lane = tid & 31, wid = tid >> 5;
    const int wm = wid >> 2, wj = wid & 3;

    for (int i = tid; i < 96*256; i += 256){
        int n = i >> 8, k = i & 255;
        int gate = n >> 5, jj = n & 31;
        float w = Wh[(size_t)k*(3*HH) + gate*HH + j0 + jj];
        float h, l; split_tf32(w, h, l);
        WSH[n*KP + k] = h;
        WSL[n*KP + k] = __float2bfloat16(l);
    }
    if (tid < 96){
        int gate = tid >> 5, jj = tid & 31;
        bhs[tid] = bh[gate*HH + j0 + jj];
    }

    float acc[4] = {0.f, 0.f, 0.f, 0.f};
    const int lr = lane >> 2, lc = lane & 3;
    const int jb = wj*8 + 2*lc;   // even base j for float2 (covers dc=0,1)

    for (int s = 0; s < NPG; s++){
        const float* hin = (s & 1) ? b1buf : b0buf;
        float*       hout= (s & 1) ? b0buf : b1buf;
        const int t = dir ? (NPG-1-s) : s;

        // prefetch x (independent of h) with float2 — dc=0,1 are adjacent
        float xv[4][3];
        #pragma unroll
        for (int dr=0; dr<2; dr++){
            const int g = g0 + wm*16 + lr + dr*8;
            const float* x = xbase + ((size_t)g*NPG + t)*(6*HH);
            float2 x0 = *(const float2*)&x[j0 + jb];
            float2 x1 = *(const float2*)&x[HH + j0 + jb];
            float2 x2 = *(const float2*)&x[2*HH + j0 + jb];
            xv[dr*2+0][0] = x0.x; xv[dr*2+1][0] = x0.y;
            xv[dr*2+0][1] = x1.x; xv[dr*2+1][1] = x1.y;
            xv[dr*2+0][2] = x2.x; xv[dr*2+1][2] = x2.y;
        }

        #pragma unroll 4
        for (int i = tid; i < 32*256; i += 256){
            int g = i >> 8, k = i & 255;
            float v = hin[(size_t)(g0+g)*HH + k];
            float h, l; split_tf32(v, h, l);
            HSH[g*KP + k] = h;
            HSL[g*KP + k] = l;
        }
        __syncthreads();

        float c[3][4];
        #pragma unroll
        for (int q=0;q<3;q++)
            #pragma unroll
            for (int p=0;p<4;p++) c[q][p]=0.f;

        const int arow = (wm*16 + lr)*KP;
        #pragma unroll 4
        for (int kt = 0; kt < 32; kt++){
            const int ac = kt*8 + lc;
            uint32_t a0 = __float_as_uint(HSH[arow + ac]);
            uint32_t a1 = __float_as_uint(HSH[arow + 8*KP + ac]);
            uint32_t a2 = __float_as_uint(HSH[arow + ac + 4]);
            uint32_t a3 = __float_as_uint(HSH[arow + 8*KP + ac + 4]);
            uint32_t l0 = __float_as_uint(HSL[arow + ac]);
            uint32_t l1 = __float_as_uint(HSL[arow + 8*KP + ac]);
            uint32_t l2 = __float_as_uint(HSL[arow + ac + 4]);
            uint32_t l3 = __float_as_uint(HSL[arow + 8*KP + ac + 4]);
            #pragma unroll
            for (int q=0;q<3;q++){
                const int brow = (q*32 + wj*8 + lr)*KP;
                uint32_t b0 = __float_as_uint(WSH[brow + ac]);
                uint32_t b1 = __float_as_uint(WSH[brow + ac + 4]);
                uint32_t bl0 = __float_as_uint(__bfloat162float(WSL[brow + ac]));
                uint32_t bl1 = __float_as_uint(__bfloat162float(WSL[brow + ac + 4]));
                MMA_TF32(c[q][0],c[q][1],c[q][2],c[q][3], a0,a1,a2,a3, b0,b1);
                MMA_TF32(c[q][0],c[q][1],c[q][2],c[q][3], a0,a1,a2,a3, bl0,bl1);
                MMA_TF32(c[q][0],c[q][1],c[q][2],c[q][3], l0,l1,l2,l3, b0,b1);
            }
        }

        #pragma unroll
        for (int dr=0; dr<2; dr++){
            const int gl = wm*16 + lr + dr*8;
            const int g = g0 + gl;
            float hv2[2];
            #pragma unroll
            for (int dc=0; dc<2; dc++){
                const int jl = jb + dc;
                const int j = j0 + jl;
                const int ci = dr*2 + dc;
                float rv = sigmoidf_(xv[ci][0] + c[0][ci] + bhs[jl]);
                float zv = sigmoidf_(xv[ci][1] + c[1][ci] + bhs[32+jl]);
                float nv = tanhf    (xv[ci][2] + rv*(c[2][ci] + bhs[64+jl]));
                float hold = HSH[gl*KP + j] + HSL[gl*KP + j];
                float hv = (1.0f - zv)*nv + zv*hold;
                acc[ci] += hv;
                hv2[dc] = hv;
            }
            *(float2*)&hout[(size_t)g*HH + j0 + jb] = make_float2(hv2[0], hv2[1]);
        }

        if (s < NPG-1){
            __threadfence();
            __syncthreads();
            if (tid == 0){
                unsigned target = (unsigned)(s+1) * 8u;
                asm volatile("red.release.gpu.add.u32 [%0], %1;"
                             :: "l"(bar), "r"(1u) : "memory");
                unsigned v;
                do {
                    asm volatile("ld.acquire.gpu.u32 %0, [%1];"
                                 : "=r"(v) : "l"(bar) : "memory");
                } while (v < target);
            }
            __syncthreads();
        }
    }

    #pragma unroll
    for (int dr=0; dr<2; dr++){
        const int g = g0 + wm*16 + lr + dr*8;
        *(float2*)&accg[(size_t)g*HH + j0 + jb] = make_float2(acc[dr*2], acc[dr*2+1]);
    }
}

__global__ void readout_k(const float* __restrict__ accf, const float* __restrict__ accb,
                          const float* __restrict__ W1, const float* __restrict__ b1,
                          const float* __restrict__ W2, const float* __restrict__ b2,
                          float* __restrict__ out)
{
    int b = blockIdx.x, j = threadIdx.x;
    __shared__ float gsh[2*HH];
    __shared__ float red[HH];
    gsh[j]      = accf[b*HH + j] * (1.0f/NPG);
    gsh[HH + j] = accb[b*HH + j] * (1.0f/NPG);
    __syncthreads();
    float y = b1[j];
    #pragma unroll 8
    for (int k=0; k<2*HH; k++)
        y = fmaf(gsh[k], W1[k*HH + j], y);
    y = fmaxf(y, 0.f);
    red[j] = y * W2[j];
    __syncthreads();
    for (int s=128; s>0; s>>=1){
        if (j < s) red[j] += red[j+s];
        __syncthreads();
    }
    if (j == 0) out[b] = red[0] + b2[0];
}

// =============================================================================
extern "C" void kernel_launch(void* const* d_in, const int* in_sizes, int n_in,
                              void* d_out, int out_size)
{
    const float* node_x = (const float*)d_in[0];
    const float* edge_x = (const float*)d_in[1];
    const int*   src    = (const int*)  d_in[2];
    const float* Wn  = (const float*)d_in[4];  const float* bn  = (const float*)d_in[5];
    const float* We  = (const float*)d_in[6];  const float* be  = (const float*)d_in[7];
    const float* Wm0 = (const float*)d_in[8];  const float* bm0 = (const float*)d_in[9];
    const float* Wm1 = (const float*)d_in[10]; const float* bm1 = (const float*)d_in[11];
    const float* Wlr = (const float*)d_in[12]; const float* blr = (const float*)d_in[13];
    const float* gbias = (const float*)d_in[14];
    const float* Wif = (const float*)d_in[15]; const float* Whf = (const float*)d_in[16];
    const float* bif = (const float*)d_in[17]; const float* bhf = (const float*)d_in[18];
    const float* Wib = (const float*)d_in[19]; const float* Whb = (const float*)d_in[20];
    const float* bib = (const float*)d_in[21]; const float* bhb = (const float*)d_in[22];
    const float* W1  = (const float*)d_in[23]; const float* b1  = (const float*)d_in[24];
    const float* W2  = (const float*)d_in[25]; const float* b2  = (const float*)d_in[26];
    float* out = (float*)d_out;

    float *p_in,*p_hn,*p_tmp,*p_cat,*p_hnl,*p_msg,*p_xgc;
    float *p_hf0,*p_hf1,*p_hb0,*p_hb1,*p_accf,*p_accb;
    float *p_WnH,*p_WnL,*p_Wm0H,*p_Wm0L,*p_Wm1H,*p_Wm1L;
    float *p_WlrH,*p_WlrL,*p_WiCH,*p_WiCL,*p_biC;
    cudaGetSymbolAddress((void**)&p_in,  g_in);
    cudaGetSymbolAddress((void**)&p_hn,  g_hn);
    cudaGetSymbolAddress((void**)&p_tmp, g_tmp);
    cudaGetSymbolAddress((void**)&p_cat, g_cat);
    cudaGetSymbolAddress((void**)&p_hnl, g_hnl);
    cudaGetSymbolAddress((void**)&p_msg, g_msg);
    cudaGetSymbolAddress((void**)&p_xgc, g_xgc);
    cudaGetSymbolAddress((void**)&p_hf0, g_hf0);
    cudaGetSymbolAddress((void**)&p_hf1, g_hf1);
    cudaGetSymbolAddress((void**)&p_hb0, g_hb0);
    cudaGetSymbolAddress((void**)&p_hb1, g_hb1);
    cudaGetSymbolAddress((void**)&p_accf, g_accf);
    cudaGetSymbolAddress((void**)&p_accb, g_accb);
    cudaGetSymbolAddress((void**)&p_WnH,  g_WnH);  cudaGetSymbolAddress((void**)&p_WnL,  g_WnL);
    cudaGetSymbolAddress((void**)&p_Wm0H, g_Wm0H); cudaGetSymbolAddress((void**)&p_Wm0L, g_Wm0L);
    cudaGetSymbolAddress((void**)&p_Wm1H, g_Wm1H); cudaGetSymbolAddress((void**)&p_Wm1L, g_Wm1L);
    cudaGetSymbolAddress((void**)&p_WlrH, g_WlrH); cudaGetSymbolAddress((void**)&p_WlrL, g_WlrL);
    cudaGetSymbolAddress((void**)&p_WiCH, g_WiCH); cudaGetSymbolAddress((void**)&p_WiCL, g_WiCL);
    cudaGetSymbolAddress((void**)&p_biC,  g_biC);

    cudaFuncSetAttribute(mma_gemm<true,false>,  cudaFuncAttributeMaxDynamicSharedMemorySize, GE_SMEM);
    cudaFuncSetAttribute(mma_gemm<false,false>, cudaFuncAttributeMaxDynamicSharedMemorySize, GE_SMEM);
    cudaFuncSetAttribute(mma_gemm<false,true>,  cudaFuncAttributeMaxDynamicSharedMemorySize, GE_SMEM);
    cudaFuncSetAttribute(gru_persist,           cudaFuncAttributeMaxDynamicSharedMemorySize, GRU_SMEM);

    // 0) one-shot weight prep (transpose + pad + hi/lo split + bias concat)
    int prep_total = SZ_WN + 2*SZ_WM + SZ_WLR + SZ_WIC + 6*HH;
    prep_all<<<(prep_total+255)/256, 256>>>(Wn, Wm0, Wm1, Wlr, Wif, Wib, bif, bib);

    // 1) node embedding
    mma_gemm<true,false><<<dim3(2,128), 256, GE_SMEM>>>(NN, HH, FN, 160,
        node_x, p_WnH, p_WnL, bn, p_in, nullptr, nullptr);

    // 2) round 1
    agg_k<false><<<NN/NPB, 256>>>(edge_x, We, be, nullptr, src, p_in, p_hn);
    mma_gemm<false,false><<<dim3(2,128), 256, GE_SMEM>>>(NN, HH, HH, HH,
        p_hn, p_Wm0H, p_Wm0L, bm0, p_tmp, nullptr, nullptr);

    // 3) round 2
    agg_k<true><<<NN/NPB, 256>>>(edge_x, We, be, p_tmp, src, p_hn, p_hn);
    mma_gemm<false,false><<<dim3(2,128), 256, GE_SMEM>>>(NN, HH, HH, HH,
        p_hn, p_Wm1H, p_Wm1L, bm1, p_tmp, nullptr, nullptr);

    // 4) final aggregate + concat + Wlr (+fused msg epilogue)
    cat_k<<<NN/NPB, 256>>>(edge_x, We, be, p_tmp, src, p_hn, p_in, p_cat);
    mma_gemm<false,true><<<dim3(2,128), 256, GE_SMEM>>>(NN, HH, 3*HH, 3*HH,
        p_cat, p_WlrH, p_WlrL, blr, p_hnl, gbias, p_msg);

    // 5) GRU setup: combined fwd|bwd gate-input GEMM (N=1536)
    init_h0_k<<<BB, HH>>>(p_hnl, p_hf0, p_hb0, p_accf, p_accb);
    mma_gemm<false,false><<<dim3(12,128), 256, GE_SMEM>>>(NN, 6*HH, HH, HH,
        p_msg, p_WiCH, p_WiCL, p_biC, p_xgc, nullptr, nullptr);

    // 6) persistent GRU (tensor-core recurrent GEMM, scoped group barriers)
    bar_reset_k<<<1,32>>>();
    gru_persist<<<GNB, 256, GRU_SMEM>>>(p_xgc, Whf, Whb, bhf, bhb,
                                        p_hf0, p_hf1, p_hb0, p_hb1, p_accf, p_accb);

    // 7) readout
    readout_k<<<BB, HH>>>(p_accf, p_accb, W1, b1, W2, b2, out);
}